// round 15
// baseline (speedup 1.0000x reference)
#include <cuda_runtime.h>

#define Hh 128
#define Ww 128
#define NB 32
#define CCH 16
#define NITER 30

#define TW 16
#define TH 16
#define IW 18
#define IH 18
#define NPX 256           // pixels per tile
#define NTILES 2048
#define NCTA 296          // 148*2; <= 2 CTAs/SM resident by launch_bounds
#define NTHR 512
#define NPIX (NB*Hh*Ww)

typedef unsigned long long ULL;

__device__ float g_bufA[NB*CCH*Hh*Ww];
__device__ float g_bufB[NB*CCH*Hh*Ww];
__device__ unsigned char g_pre[NB*Hh*Ww];
__device__ unsigned char g_alive[NB*Hh*Ww];
__device__ unsigned g_counts[64];           // epoch-indexed grid-barrier counters

__device__ __forceinline__ ULL pk2(float a, float b){
    ULL r; asm("mov.b64 %0, {%1,%2};" : "=l"(r) : "f"(a), "f"(b)); return r;
}
__device__ __forceinline__ void fma2(ULL &d, ULL a, ULL b){
    asm("fma.rn.f32x2 %0, %1, %2, %0;" : "+l"(d) : "l"(a), "l"(b));
}
__device__ __forceinline__ float lo2(ULL v){ return __uint_as_float((unsigned)v); }
__device__ __forceinline__ float hi2(ULL v){ return __uint_as_float((unsigned)(v>>32)); }

// grid-wide barrier, epoch e (one-shot counter per epoch; zeroed by init_kernel)
__device__ __forceinline__ void grid_sync(int e){
    __syncthreads();
    if (threadIdx.x == 0) {
        __threadfence();                      // release: my writes visible before arrive
        atomicAdd(&g_counts[e], 1u);
        while (__ldcg(&g_counts[e]) < NCTA) __nanosleep(64);
    }
    __syncthreads();                          // all threads held until release observed
}

__global__ void init_kernel(const float* __restrict__ inp){
    int p = blockIdx.x*blockDim.x + threadIdx.x;
    if (p < 64) g_counts[p] = 0;
    const int total = NB*CCH*Hh*Ww;
    if (p >= total) return;
    int hw = p % (Hh*Ww);
    int c  = (p / (Hh*Ww)) % CCH;
    int n  = p / (CCH*Hh*Ww);
    float v;
    if (c == 0)       v = 1.0f - inp[(n*10 + 0)*Hh*Ww + hw];
    else if (c <= 10) v = inp[(n*10 + (c-1))*Hh*Ww + hw];
    else              v = 0.0f;
    g_bufA[p] = v;
    if (c == 0) g_alive[n*Hh*Ww + hw] = 1;
}

// smem float layout (16448 floats = 65792 B):
//   sw1f: [0, 2304)      w1 transposed [k][o]
//   sw2f: [2304, 3072)   w2 transposed [o][j]
//   spf:  [3072, 11264)  sobel rows [32][256]; after GEMM1: H rows 0..31
//   scf:  [11264, 16448) cell tile 16*18*18; after GEMM1: H rows 32..47
__global__ void __launch_bounds__(NTHR, 2)
ca_persistent(const float* __restrict__ w1, const float* __restrict__ w2,
              float* __restrict__ outfinal)
{
    extern __shared__ float smem_f[];
    float* sw1f = smem_f;
    float* sw2f = smem_f + 2304;
    float* spf  = smem_f + 3072;
    float* scf  = smem_f + 11264;

    const int tid = threadIdx.x;

    // ---- stage weights ONCE per run ----
    for (int i = tid; i < 48*48; i += NTHR) {
        int k = i / 48, o = i % 48;
        sw1f[i] = w1[o*48 + k];
    }
    for (int i = tid; i < 48*16; i += NTHR) {
        int o = i >> 4, j = i & 15;
        sw2f[i] = w2[j*48 + o];
    }
    // no barrier needed before first use beyond the in-loop ones below
    __syncthreads();

    #pragma unroll 1
    for (int it = 0; it < NITER; it++) {
        const float* __restrict__ src = (it & 1) ? g_bufB : g_bufA;
        float* __restrict__ dst       = (it & 1) ? g_bufA : g_bufB;

        // ================= STEP PHASE =================
        #pragma unroll 1
        for (int tile = blockIdx.x; tile < NTILES; tile += NCTA) {
            const int n   = tile >> 6;
            const int rem = tile & 63;
            const int gy0 = (rem >> 3) * TH;
            const int gx0 = (rem & 7) * TW;

            // ---- stage cell tile (masked, zero-padded halo) ----
            const unsigned char* arow = g_alive + n*Hh*Ww;
            for (int i = tid; i < CCH*IH*IW; i += NTHR) {
                int sx = i % IW;
                int t  = i / IW;
                int sy = t % IH;
                int c  = t / IH;
                int gx = gx0 + sx - 1, gy = gy0 + sy - 1;
                float v = 0.0f;
                if ((unsigned)gx < (unsigned)Ww && (unsigned)gy < (unsigned)Hh) {
                    int hw = gy*Ww + gx;
                    if (__ldcg(arow + hw))
                        v = __ldcg(src + (size_t)(n*CCH + c)*(Hh*Ww) + hw);
                }
                scf[(c*IH + sy)*IW + sx] = v;
            }
            __syncthreads();

            // ---- perception: sobel -> spf rows (cell stays in scf); 4 thr/pair ----
            {
                const int pair = tid & 127;
                const int q    = tid >> 7;           // 0..3 -> 4 channels each
                const int py = pair >> 3, px2 = pair & 7;
                const int sy = py + 1;
                #pragma unroll
                for (int cc = 0; cc < 4; cc++) {
                    int c = 4*q + cc;
                    const float2* r0 = (const float2*)(scf + (c*IH + sy - 1)*IW + 2*px2);
                    const float2* r1 = (const float2*)((const float*)r0 + IW);
                    const float2* r2 = (const float2*)((const float*)r1 + IW);
                    float2 v00 = r0[0], v01 = r0[1];
                    float2 v10 = r1[0], v11 = r1[1];
                    float2 v20 = r2[0], v21 = r2[1];
                    float a0=v00.x,a1=v00.y,a2=v01.x,a3=v01.y;
                    float m0=v10.x,m1=v10.y,m2=v11.x,m3=v11.y;
                    float q0=v20.x,q1=v20.y,q2=v21.x,q3=v21.y;
                    float gxl = ((a2 - a0) + 2.f*(m2 - m0) + (q2 - q0)) * 0.125f;
                    float gxh = ((a3 - a1) + 2.f*(m3 - m1) + (q3 - q1)) * 0.125f;
                    float gyl = ((q0 - a0) + 2.f*(q1 - a1) + (q2 - a2)) * 0.125f;
                    float gyh = ((q1 - a1) + 2.f*(q2 - a2) + (q3 - a3)) * 0.125f;
                    *(float2*)(spf + c*NPX + 2*pair)        = make_float2(gxl, gxh);
                    *(float2*)(spf + (16 + c)*NPX + 2*pair) = make_float2(gyl, gyh);
                    if (c == 0) {
                        float t0 = fmaxf(fmaxf(a0,a1),a2);
                        float t1 = fmaxf(fmaxf(m0,m1),m2);
                        float t2 = fmaxf(fmaxf(q0,q1),q2);
                        float pl = fmaxf(fmaxf(t0,t1),t2);
                        float u0 = fmaxf(fmaxf(a1,a2),a3);
                        float u1 = fmaxf(fmaxf(m1,m2),m3);
                        float u2 = fmaxf(fmaxf(q1,q2),q3);
                        float ph = fmaxf(fmaxf(u0,u1),u2);
                        uchar2 pm;
                        pm.x = (pl > 0.1f) ? 1 : 0;
                        pm.y = (ph > 0.1f) ? 1 : 0;
                        *reinterpret_cast<uchar2*>(g_pre + (n*Hh + gy0 + py)*Ww + gx0 + 2*px2) = pm;
                    }
                }
            }
            __syncthreads();

            // ---- GEMM1: H = relu(W1*perc); thread = (g in 128 px-lanes, ob of 12 o) ----
            {
                const int g  = tid & 127;    // px = g, g+128
                const int ob = tid >> 7;     // o = 12*ob .. 12*ob+11
                ULL acc[2][6];
                #pragma unroll
                for (int m = 0; m < 2; m++)
                    #pragma unroll
                    for (int j = 0; j < 6; j++) acc[m][j] = 0ull;

                const int off0 = (((g       ) >> 4) + 1)*IW + ((g       ) & 15) + 1;
                const int off1 = (((g + 128 ) >> 4) + 1)*IW + ((g + 128 ) & 15) + 1;

                #pragma unroll 4
                for (int k = 0; k < 16; k++) {
                    float p0 = scf[k*(IH*IW) + off0];
                    float p1 = scf[k*(IH*IW) + off1];
                    ULL s0 = pk2(p0,p0), s1 = pk2(p1,p1);
                    const ulonglong2* wv = (const ulonglong2*)(sw1f + k*48 + 12*ob);
                    ulonglong2 w0 = wv[0], w1v = wv[1], w2v = wv[2];
                    fma2(acc[0][0], s0, w0.x);  fma2(acc[1][0], s1, w0.x);
                    fma2(acc[0][1], s0, w0.y);  fma2(acc[1][1], s1, w0.y);
                    fma2(acc[0][2], s0, w1v.x); fma2(acc[1][2], s1, w1v.x);
                    fma2(acc[0][3], s0, w1v.y); fma2(acc[1][3], s1, w1v.y);
                    fma2(acc[0][4], s0, w2v.x); fma2(acc[1][4], s1, w2v.x);
                    fma2(acc[0][5], s0, w2v.y); fma2(acc[1][5], s1, w2v.y);
                }
                #pragma unroll 4
                for (int k2 = 0; k2 < 32; k2++) {
                    const float* pr = spf + k2*NPX + g;
                    float p0 = pr[0], p1 = pr[128];
                    ULL s0 = pk2(p0,p0), s1 = pk2(p1,p1);
                    const ulonglong2* wv = (const ulonglong2*)(sw1f + (16 + k2)*48 + 12*ob);
                    ulonglong2 w0 = wv[0], w1v = wv[1], w2v = wv[2];
                    fma2(acc[0][0], s0, w0.x);  fma2(acc[1][0], s1, w0.x);
                    fma2(acc[0][1], s0, w0.y);  fma2(acc[1][1], s1, w0.y);
                    fma2(acc[0][2], s0, w1v.x); fma2(acc[1][2], s1, w1v.x);
                    fma2(acc[0][3], s0, w1v.y); fma2(acc[1][3], s1, w1v.y);
                    fma2(acc[0][4], s0, w2v.x); fma2(acc[1][4], s1, w2v.x);
                    fma2(acc[0][5], s0, w2v.y); fma2(acc[1][5], s1, w2v.y);
                }
                __syncthreads();   // sp/sc reads done before H overwrites
                #pragma unroll
                for (int op = 0; op < 6; op++) {
                    int o = 12*ob + 2*op;          // even; (o,o+1) never straddles 32
                    float* r0 = (o < 32) ? (spf + o*NPX) : (scf + (o - 32)*NPX);
                    float* r1 = r0 + NPX;
                    r0[g]       = fmaxf(lo2(acc[0][op]), 0.f);
                    r0[g + 128] = fmaxf(lo2(acc[1][op]), 0.f);
                    r1[g]       = fmaxf(hi2(acc[0][op]), 0.f);
                    r1[g + 128] = fmaxf(hi2(acc[1][op]), 0.f);
                }
            }
            __syncthreads();

            // ---- GEMM2: cur = W2*H + residual; thread = (g2 in 128, jg of 4 j) ----
            {
                const int g2 = tid & 127;    // px = g2, g2+128
                const int jg = tid >> 7;     // j = 4*jg .. 4*jg+3
                const int pxA = g2, pxB = g2 + 128;
                const int pyA = pxA >> 4, sxA = pxA & 15;
                const int pyB = pxB >> 4, sxB = pxB & 15;
                const int hwA = (gy0 + pyA)*Ww + gx0 + sxA;
                const int hwB = (gy0 + pyB)*Ww + gx0 + sxB;

                float rA[4], rB[4];
                {
                    const unsigned char aA = __ldcg(arow + hwA);
                    const unsigned char aB = __ldcg(arow + hwB);
                    #pragma unroll
                    for (int jj = 0; jj < 4; jj++) {
                        int j = 4*jg + jj;
                        const float* sj = src + (size_t)(n*CCH + j)*(Hh*Ww);
                        rA[jj] = aA ? __ldcg(sj + hwA) : 0.0f;
                        rB[jj] = aB ? __ldcg(sj + hwB) : 0.0f;
                    }
                }

                ULL cA[2], cB[2];
                cA[0] = cA[1] = cB[0] = cB[1] = 0ull;

                #pragma unroll 8
                for (int o = 0; o < 32; o++) {
                    const float* hs = spf + o*NPX;
                    float ha = hs[g2], hb = hs[g2 + 128];
                    ULL sa = pk2(ha,ha), sb = pk2(hb,hb);
                    const ulonglong2* wv = (const ulonglong2*)(sw2f + o*16 + 4*jg);
                    ulonglong2 w0 = wv[0];
                    fma2(cA[0], sa, w0.x); fma2(cA[1], sa, w0.y);
                    fma2(cB[0], sb, w0.x); fma2(cB[1], sb, w0.y);
                }
                #pragma unroll 8
                for (int o = 32; o < 48; o++) {
                    const float* hs = scf + (o - 32)*NPX;
                    float ha = hs[g2], hb = hs[g2 + 128];
                    ULL sa = pk2(ha,ha), sb = pk2(hb,hb);
                    const ulonglong2* wv = (const ulonglong2*)(sw2f + o*16 + 4*jg);
                    ulonglong2 w0 = wv[0];
                    fma2(cA[0], sa, w0.x); fma2(cA[1], sa, w0.y);
                    fma2(cB[0], sb, w0.x); fma2(cB[1], sb, w0.y);
                }

                #pragma unroll
                for (int q = 0; q < 2; q++) {
                    int j = 4*jg + 2*q;
                    float* d0 = dst + (size_t)(n*CCH + j)*(Hh*Ww);
                    float* d1 = d0 + Hh*Ww;
                    d0[hwA] = lo2(cA[q]) + rA[2*q];
                    d1[hwA] = hi2(cA[q]) + rA[2*q + 1];
                    d0[hwB] = lo2(cB[q]) + rB[2*q];
                    d1[hwB] = hi2(cB[q]) + rB[2*q + 1];
                }
            }
            __syncthreads();   // H reads done before next tile's staging
        }

        grid_sync(2*it);       // all step writes (dst, g_pre) visible

        // ================= ALIVE PHASE =================
        {
            const float* __restrict__ cur = dst;
            const int last = (it == NITER-1);
            for (int p = blockIdx.x*NTHR + tid; p < NPIX; p += NCTA*NTHR) {
                int x = p % Ww;
                int y = (p / Ww) % Hh;
                int n = p / (Hh*Ww);
                const float* c0 = cur + (size_t)n*CCH*Hh*Ww;
                float m = -1e30f;
                int y0 = (y > 0) ? y - 1 : 0, y1 = (y < Hh-1) ? y + 1 : Hh-1;
                int x0 = (x > 0) ? x - 1 : 0, x1 = (x < Ww-1) ? x + 1 : Ww-1;
                for (int yy = y0; yy <= y1; yy++) {
                    const float* row = c0 + yy*Ww;
                    for (int xx = x0; xx <= x1; xx++)
                        m = fmaxf(m, __ldcg(row + xx));
                }
                bool alive = (m > 0.1f) && (__ldcg(g_pre + p) != 0);
                if (!last) {
                    g_alive[p] = alive ? 1 : 0;
                } else {
                    size_t base = ((size_t)n*CCH)*Hh*Ww + (size_t)y*Ww + x;
                    #pragma unroll
                    for (int c = 1; c <= 10; c++) {
                        float v = alive ? __ldcg(cur + base + (size_t)c*Hh*Ww) : 0.0f;
                        outfinal[(((size_t)n*10 + (c-1))*Hh + y)*Ww + x] = v;
                    }
                }
            }
        }

        if (it < NITER-1) grid_sync(2*it + 1);   // g_alive visible to next step
    }
}

extern "C" void kernel_launch(void* const* d_in, const int* in_sizes, int n_in,
                              void* d_out, int out_size)
{
    const float *inp = nullptr, *w1 = nullptr, *w2 = nullptr;
    for (int i = 0; i < n_in; i++) {
        if (in_sizes[i] == 48*48)      w1 = (const float*)d_in[i];
        else if (in_sizes[i] == 16*48) w2 = (const float*)d_in[i];
        else                           inp = (const float*)d_in[i];
    }
    float* out = (float*)d_out;

    const int smemBytes = 16448*4;   // 65792 B
    cudaFuncSetAttribute(ca_persistent, cudaFuncAttributeMaxDynamicSharedMemorySize, smemBytes);

    init_kernel<<<(NB*CCH*Hh*Ww + 255)/256, 256>>>(inp);
    ca_persistent<<<NCTA, NTHR, smemBytes>>>(w1, w2, out);
}

// round 16
// speedup vs baseline: 1.1110x; 1.1110x over previous
#include <cuda_runtime.h>

#define Hh 128
#define Ww 128
#define NB 32
#define CCH 16
#define NITER 30

#define TW 16
#define TH 16
#define IW 18
#define IH 18
#define NPX 256           // pixels per tile
#define NTILES 2048
#define NCTA 296          // 148 * 2 (512-thread CTAs)
#define NTHR 512

typedef unsigned long long ULL;

__device__ float g_bufA[NB*CCH*Hh*Ww];
__device__ float g_bufB[NB*CCH*Hh*Ww];
__device__ unsigned char g_pre[NB*Hh*Ww];
__device__ unsigned char g_alive[NB*Hh*Ww];

__device__ __forceinline__ ULL pk2(float a, float b){
    ULL r; asm("mov.b64 %0, {%1,%2};" : "=l"(r) : "f"(a), "f"(b)); return r;
}
__device__ __forceinline__ void fma2(ULL &d, ULL a, ULL b){
    asm("fma.rn.f32x2 %0, %1, %2, %0;" : "+l"(d) : "l"(a), "l"(b));
}
__device__ __forceinline__ float lo2(ULL v){ return __uint_as_float((unsigned)v); }
__device__ __forceinline__ float hi2(ULL v){ return __uint_as_float((unsigned)(v>>32)); }

__global__ void init_kernel(const float* __restrict__ inp){
    int p = blockIdx.x*blockDim.x + threadIdx.x;
    const int total = NB*CCH*Hh*Ww;
    if (p >= total) return;
    int hw = p % (Hh*Ww);
    int c  = (p / (Hh*Ww)) % CCH;
    int n  = p / (CCH*Hh*Ww);
    float v;
    if (c == 0)       v = 1.0f - inp[(n*10 + 0)*Hh*Ww + hw];
    else if (c <= 10) v = inp[(n*10 + (c-1))*Hh*Ww + hw];
    else              v = 0.0f;
    g_bufA[p] = v;
    if (c == 0) g_alive[n*Hh*Ww + hw] = 1;
}

// smem float layout (16448 floats = 65792 B):
//   sw1f: [0, 2304)        w1 transposed [k][o]
//   sw2f: [2304, 3072)     w2 transposed [o][j]
//   spf:  [3072, 11264)    sobel rows [32][256]; after GEMM1: H rows 0..31
//   scf:  [11264, 16448)   cell tile 16*18*18; after GEMM1: H rows 32..47
__global__ void __launch_bounds__(NTHR, 2)
step_kernel(const float* __restrict__ w1, const float* __restrict__ w2, int parity)
{
    extern __shared__ float smem_f[];
    float* sw1f = smem_f;
    float* sw2f = smem_f + 2304;
    float* spf  = smem_f + 3072;
    float* scf  = smem_f + 11264;

    const float* __restrict__ src = parity ? g_bufB : g_bufA;
    float* __restrict__ dst       = parity ? g_bufA : g_bufB;

    const int tid = threadIdx.x;

    // ---- stage weights ONCE per CTA (plain floats, transposed) ----
    for (int i = tid; i < 48*48; i += NTHR) {
        int k = i / 48, o = i % 48;
        sw1f[i] = w1[o*48 + k];
    }
    for (int i = tid; i < 48*16; i += NTHR) {
        int o = i >> 4, j = i & 15;
        sw2f[i] = w2[j*48 + o];
    }

    #pragma unroll 1
    for (int tile = blockIdx.x; tile < NTILES; tile += NCTA) {
        const int n   = tile >> 6;
        const int rem = tile & 63;
        const int gy0 = (rem >> 3) * TH;
        const int gx0 = (rem & 7) * TW;

        // ---- stage cell tile (masked, zero-padded halo) ----
        const unsigned char* arow = g_alive + n*Hh*Ww;
        for (int i = tid; i < CCH*IH*IW; i += NTHR) {
            int sx = i % IW;
            int t  = i / IW;
            int sy = t % IH;
            int c  = t / IH;
            int gx = gx0 + sx - 1, gy = gy0 + sy - 1;
            float v = 0.0f;
            if ((unsigned)gx < (unsigned)Ww && (unsigned)gy < (unsigned)Hh) {
                int hw = gy*Ww + gx;
                if (arow[hw])
                    v = src[(size_t)(n*CCH + c)*(Hh*Ww) + hw];
            }
            scf[(c*IH + sy)*IW + sx] = v;
        }
        __syncthreads();

        // ---- perception: sobel -> spf rows (cell stays in scf); 4 thr/pair ----
        {
            const int pair = tid & 127;          // 128 pixel-pairs
            const int q    = tid >> 7;           // 0..3 -> 4 channels each
            const int py = pair >> 3, px2 = pair & 7;
            const int sy = py + 1;
            #pragma unroll
            for (int cc = 0; cc < 4; cc++) {
                int c = 4*q + cc;
                const float2* r0 = (const float2*)(scf + (c*IH + sy - 1)*IW + 2*px2);
                const float2* r1 = (const float2*)((const float*)r0 + IW);
                const float2* r2 = (const float2*)((const float*)r1 + IW);
                float2 v00 = r0[0], v01 = r0[1];
                float2 v10 = r1[0], v11 = r1[1];
                float2 v20 = r2[0], v21 = r2[1];
                float a0=v00.x,a1=v00.y,a2=v01.x,a3=v01.y;
                float m0=v10.x,m1=v10.y,m2=v11.x,m3=v11.y;
                float q0=v20.x,q1=v20.y,q2=v21.x,q3=v21.y;
                float gxl = ((a2 - a0) + 2.f*(m2 - m0) + (q2 - q0)) * 0.125f;
                float gxh = ((a3 - a1) + 2.f*(m3 - m1) + (q3 - q1)) * 0.125f;
                float gyl = ((q0 - a0) + 2.f*(q1 - a1) + (q2 - a2)) * 0.125f;
                float gyh = ((q1 - a1) + 2.f*(q2 - a2) + (q3 - a3)) * 0.125f;
                *(float2*)(spf + c*NPX + 2*pair)        = make_float2(gxl, gxh);
                *(float2*)(spf + (16 + c)*NPX + 2*pair) = make_float2(gyl, gyh);
                if (c == 0) {
                    float t0 = fmaxf(fmaxf(a0,a1),a2);
                    float t1 = fmaxf(fmaxf(m0,m1),m2);
                    float t2 = fmaxf(fmaxf(q0,q1),q2);
                    float pl = fmaxf(fmaxf(t0,t1),t2);
                    float u0 = fmaxf(fmaxf(a1,a2),a3);
                    float u1 = fmaxf(fmaxf(m1,m2),m3);
                    float u2 = fmaxf(fmaxf(q1,q2),q3);
                    float ph = fmaxf(fmaxf(u0,u1),u2);
                    uchar2 pm;
                    pm.x = (pl > 0.1f) ? 1 : 0;
                    pm.y = (ph > 0.1f) ? 1 : 0;
                    *reinterpret_cast<uchar2*>(g_pre + (n*Hh + gy0 + py)*Ww + gx0 + 2*px2) = pm;
                }
            }
        }
        __syncthreads();

        // ---- GEMM1: H = relu(W1*perc); thread = (g in 128 px-lanes, ob of 12 o) ----
        {
            const int g  = tid & 127;    // px = g, g+128
            const int ob = tid >> 7;     // o = 12*ob .. 12*ob+11
            ULL acc[2][6];
            #pragma unroll
            for (int m = 0; m < 2; m++)
                #pragma unroll
                for (int j = 0; j < 6; j++) acc[m][j] = 0ull;

            const int off0 = (((g       ) >> 4) + 1)*IW + ((g       ) & 15) + 1;
            const int off1 = (((g + 128 ) >> 4) + 1)*IW + ((g + 128 ) & 15) + 1;

            // part A: k = 0..15, cell from scf
            #pragma unroll 4
            for (int k = 0; k < 16; k++) {
                float p0 = scf[k*(IH*IW) + off0];
                float p1 = scf[k*(IH*IW) + off1];
                ULL s0 = pk2(p0,p0), s1 = pk2(p1,p1);
                const ulonglong2* wv = (const ulonglong2*)(sw1f + k*48 + 12*ob);
                ulonglong2 w0 = wv[0], w1v = wv[1], w2v = wv[2];
                fma2(acc[0][0], s0, w0.x);  fma2(acc[1][0], s1, w0.x);
                fma2(acc[0][1], s0, w0.y);  fma2(acc[1][1], s1, w0.y);
                fma2(acc[0][2], s0, w1v.x); fma2(acc[1][2], s1, w1v.x);
                fma2(acc[0][3], s0, w1v.y); fma2(acc[1][3], s1, w1v.y);
                fma2(acc[0][4], s0, w2v.x); fma2(acc[1][4], s1, w2v.x);
                fma2(acc[0][5], s0, w2v.y); fma2(acc[1][5], s1, w2v.y);
            }
            // part B: k = 16..47, sobel from spf rows 0..31
            #pragma unroll 4
            for (int k2 = 0; k2 < 32; k2++) {
                const float* pr = spf + k2*NPX + g;
                float p0 = pr[0], p1 = pr[128];
                ULL s0 = pk2(p0,p0), s1 = pk2(p1,p1);
                const ulonglong2* wv = (const ulonglong2*)(sw1f + (16 + k2)*48 + 12*ob);
                ulonglong2 w0 = wv[0], w1v = wv[1], w2v = wv[2];
                fma2(acc[0][0], s0, w0.x);  fma2(acc[1][0], s1, w0.x);
                fma2(acc[0][1], s0, w0.y);  fma2(acc[1][1], s1, w0.y);
                fma2(acc[0][2], s0, w1v.x); fma2(acc[1][2], s1, w1v.x);
                fma2(acc[0][3], s0, w1v.y); fma2(acc[1][3], s1, w1v.y);
                fma2(acc[0][4], s0, w2v.x); fma2(acc[1][4], s1, w2v.x);
                fma2(acc[0][5], s0, w2v.y); fma2(acc[1][5], s1, w2v.y);
            }
            __syncthreads();   // sp/sc reads done before H overwrites
            // store H: rows 0..31 -> spf, rows 32..47 -> scf
            #pragma unroll
            for (int op = 0; op < 6; op++) {
                int o = 12*ob + 2*op;          // even; pair (o,o+1) never straddles 32
                float* r0 = (o < 32) ? (spf + o*NPX) : (scf + (o - 32)*NPX);
                float* r1 = r0 + NPX;
                r0[g]       = fmaxf(lo2(acc[0][op]), 0.f);
                r0[g + 128] = fmaxf(lo2(acc[1][op]), 0.f);
                r1[g]       = fmaxf(hi2(acc[0][op]), 0.f);
                r1[g + 128] = fmaxf(hi2(acc[1][op]), 0.f);
            }
        }
        __syncthreads();

        // ---- GEMM2: cur = W2*H + residual; thread = (g2 in 128, jg of 4 j) ----
        {
            const int g2 = tid & 127;    // px = g2, g2+128
            const int jg = tid >> 7;     // j = 4*jg .. 4*jg+3
            const int pxA = g2, pxB = g2 + 128;
            const int pyA = pxA >> 4, sxA = pxA & 15;
            const int pyB = pxB >> 4, sxB = pxB & 15;
            const int hwA = (gy0 + pyA)*Ww + gx0 + sxA;
            const int hwB = (gy0 + pyB)*Ww + gx0 + sxB;

            // residual: masked cell re-read from global (L2-resident)
            float rA[4], rB[4];
            {
                const unsigned char aA = arow[hwA];
                const unsigned char aB = arow[hwB];
                #pragma unroll
                for (int jj = 0; jj < 4; jj++) {
                    int j = 4*jg + jj;
                    const float* sj = src + (size_t)(n*CCH + j)*(Hh*Ww);
                    rA[jj] = aA ? sj[hwA] : 0.0f;
                    rB[jj] = aB ? sj[hwB] : 0.0f;
                }
            }

            ULL cA[2], cB[2];
            cA[0] = cA[1] = cB[0] = cB[1] = 0ull;

            #pragma unroll 8
            for (int o = 0; o < 32; o++) {
                const float* hs = spf + o*NPX;
                float ha = hs[g2], hb = hs[g2 + 128];
                ULL sa = pk2(ha,ha), sb = pk2(hb,hb);
                const ulonglong2* wv = (const ulonglong2*)(sw2f + o*16 + 4*jg);
                ulonglong2 w0 = wv[0];
                fma2(cA[0], sa, w0.x); fma2(cA[1], sa, w0.y);
                fma2(cB[0], sb, w0.x); fma2(cB[1], sb, w0.y);
            }
            #pragma unroll 8
            for (int o = 32; o < 48; o++) {
                const float* hs = scf + (o - 32)*NPX;
                float ha = hs[g2], hb = hs[g2 + 128];
                ULL sa = pk2(ha,ha), sb = pk2(hb,hb);
                const ulonglong2* wv = (const ulonglong2*)(sw2f + o*16 + 4*jg);
                ulonglong2 w0 = wv[0];
                fma2(cA[0], sa, w0.x); fma2(cA[1], sa, w0.y);
                fma2(cB[0], sb, w0.x); fma2(cB[1], sb, w0.y);
            }

            // store with residual
            #pragma unroll
            for (int q = 0; q < 2; q++) {
                int j = 4*jg + 2*q;
                float* d0 = dst + (size_t)(n*CCH + j)*(Hh*Ww);
                float* d1 = d0 + Hh*Ww;
                d0[hwA] = lo2(cA[q]) + rA[2*q];
                d1[hwA] = hi2(cA[q]) + rA[2*q + 1];
                d0[hwB] = lo2(cB[q]) + rB[2*q];
                d1[hwB] = hi2(cB[q]) + rB[2*q + 1];
            }
        }
        __syncthreads();   // H reads done before next tile's staging
    }
}

// Vectorized alive: 1 thread = 4 x-adjacent pixels. 9 loads vs 36.
__global__ void alive_kernel(float* __restrict__ outfinal, int parity, int writeOut)
{
    const float* __restrict__ cur = parity ? g_bufA : g_bufB;
    int t = blockIdx.x*blockDim.x + threadIdx.x;    // over NB*Hh*Ww/4
    if (t >= NB*Hh*Ww/4) return;
    const int x0 = (t % (Ww/4)) * 4;
    const int y  = (t / (Ww/4)) % Hh;
    const int n  = t / (Hh*Ww/4);
    const float* c0 = cur + (size_t)n*CCH*Hh*Ww;

    float m0 = -1e30f, m1 = -1e30f, m2 = -1e30f, m3 = -1e30f;
    const int yA = (y > 0) ? y - 1 : y;
    const int yB = (y < Hh-1) ? y + 1 : y;
    #pragma unroll
    for (int yy = yA; yy <= yB; yy++) {
        const float* row = c0 + yy*Ww;
        float4 v = *reinterpret_cast<const float4*>(row + x0);
        float l = (x0 > 0)      ? row[x0 - 1] : -1e30f;
        float r = (x0 + 4 < Ww) ? row[x0 + 4] : -1e30f;
        m0 = fmaxf(m0, fmaxf(l,   fmaxf(v.x, v.y)));
        m1 = fmaxf(m1, fmaxf(v.x, fmaxf(v.y, v.z)));
        m2 = fmaxf(m2, fmaxf(v.y, fmaxf(v.z, v.w)));
        m3 = fmaxf(m3, fmaxf(v.z, fmaxf(v.w, r)));
    }
    const int p = (n*Hh + y)*Ww + x0;
    uchar4 pre = *reinterpret_cast<const uchar4*>(g_pre + p);
    uchar4 al;
    al.x = (m0 > 0.1f && pre.x) ? 1 : 0;
    al.y = (m1 > 0.1f && pre.y) ? 1 : 0;
    al.z = (m2 > 0.1f && pre.z) ? 1 : 0;
    al.w = (m3 > 0.1f && pre.w) ? 1 : 0;
    *reinterpret_cast<uchar4*>(g_alive + p) = al;

    if (writeOut) {
        size_t base = ((size_t)n*CCH)*Hh*Ww + (size_t)y*Ww + x0;
        #pragma unroll
        for (int c = 1; c <= 10; c++) {
            float4 v = *reinterpret_cast<const float4*>(cur + base + (size_t)c*Hh*Ww);
            float4 o;
            o.x = al.x ? v.x : 0.0f;
            o.y = al.y ? v.y : 0.0f;
            o.z = al.z ? v.z : 0.0f;
            o.w = al.w ? v.w : 0.0f;
            *reinterpret_cast<float4*>(outfinal + (((size_t)n*10 + (c-1))*Hh + y)*Ww + x0) = o;
        }
    }
}

extern "C" void kernel_launch(void* const* d_in, const int* in_sizes, int n_in,
                              void* d_out, int out_size)
{
    const float *inp = nullptr, *w1 = nullptr, *w2 = nullptr;
    for (int i = 0; i < n_in; i++) {
        if (in_sizes[i] == 48*48)      w1 = (const float*)d_in[i];
        else if (in_sizes[i] == 16*48) w2 = (const float*)d_in[i];
        else                           inp = (const float*)d_in[i];
    }
    float* out = (float*)d_out;

    const int smemBytes = 16448*4;   // 65792 B
    cudaFuncSetAttribute(step_kernel, cudaFuncAttributeMaxDynamicSharedMemorySize, smemBytes);

    init_kernel<<<(NB*CCH*Hh*Ww + 255)/256, 256>>>(inp);

    const int g2 = (NB*Hh*Ww/4 + 255)/256;
    for (int it = 0; it < NITER; it++) {
        int parity = it & 1;
        step_kernel<<<NCTA, NTHR, smemBytes>>>(w1, w2, parity);
        alive_kernel<<<g2, 256>>>(out, parity, (it == NITER-1) ? 1 : 0);
    }
}

// round 17
// speedup vs baseline: 1.1218x; 1.0098x over previous
#include <cuda_runtime.h>

#define Hh 128
#define Ww 128
#define NB 32
#define CCH 16
#define NITER 30

#define TW 16
#define TH 16
#define IW 18
#define IH 18
#define NPX 256           // pixels per tile
#define NTILES 2048
#define NCTA 296          // 148 * 2 (512-thread CTAs)
#define NTHR 512

typedef unsigned long long ULL;

__device__ float g_bufA[NB*CCH*Hh*Ww];
__device__ float g_bufB[NB*CCH*Hh*Ww];
__device__ unsigned char g_pre[NB*Hh*Ww];
__device__ unsigned char g_alive[NB*Hh*Ww];

__device__ __forceinline__ ULL pk2(float a, float b){
    ULL r; asm("mov.b64 %0, {%1,%2};" : "=l"(r) : "f"(a), "f"(b)); return r;
}
__device__ __forceinline__ void fma2(ULL &d, ULL a, ULL b){
    asm("fma.rn.f32x2 %0, %1, %2, %0;" : "+l"(d) : "l"(a), "l"(b));
}
__device__ __forceinline__ float lo2(ULL v){ return __uint_as_float((unsigned)v); }
__device__ __forceinline__ float hi2(ULL v){ return __uint_as_float((unsigned)(v>>32)); }

__global__ void init_kernel(const float* __restrict__ inp){
    int p = blockIdx.x*blockDim.x + threadIdx.x;
    const int total = NB*CCH*Hh*Ww;
    if (p >= total) return;
    int hw = p % (Hh*Ww);
    int c  = (p / (Hh*Ww)) % CCH;
    int n  = p / (CCH*Hh*Ww);
    float v;
    if (c == 0)       v = 1.0f - inp[(n*10 + 0)*Hh*Ww + hw];
    else if (c <= 10) v = inp[(n*10 + (c-1))*Hh*Ww + hw];
    else              v = 0.0f;
    g_bufA[p] = v;
    if (c == 0) g_alive[n*Hh*Ww + hw] = 1;
}

// smem float layout (20544 floats = 82176 B):
//   sw1f: [0, 2304)        w1 transposed [k][o]
//   sw2f: [2304, 3072)     w2 transposed [o][j]
//   spf:  [3072, 11264)    sobel rows [32][256]; after GEMM1: H rows 0..31
//   scf:  [11264, 16448)   cell tile 16*18*18 (PRESERVED through GEMM2 for residual)
//   shf:  [16448, 20544)   H rows 32..47 [16][256]
__global__ void __launch_bounds__(NTHR, 2)
step_kernel(const float* __restrict__ w1, const float* __restrict__ w2, int parity)
{
    extern __shared__ float smem_f[];
    float* sw1f = smem_f;
    float* sw2f = smem_f + 2304;
    float* spf  = smem_f + 3072;
    float* scf  = smem_f + 11264;
    float* shf  = smem_f + 16448;

    const float* __restrict__ src = parity ? g_bufB : g_bufA;
    float* __restrict__ dst       = parity ? g_bufA : g_bufB;

    const int tid = threadIdx.x;

    // ---- stage weights ONCE per CTA (plain floats, transposed) ----
    for (int i = tid; i < 48*48; i += NTHR) {
        int k = i / 48, o = i % 48;
        sw1f[i] = w1[o*48 + k];
    }
    for (int i = tid; i < 48*16; i += NTHR) {
        int o = i >> 4, j = i & 15;
        sw2f[i] = w2[j*48 + o];
    }

    #pragma unroll 1
    for (int tile = blockIdx.x; tile < NTILES; tile += NCTA) {
        const int n   = tile >> 6;
        const int rem = tile & 63;
        const int gy0 = (rem >> 3) * TH;
        const int gx0 = (rem & 7) * TW;

        // ---- stage cell tile (masked, zero-padded halo) ----
        const unsigned char* arow = g_alive + n*Hh*Ww;
        for (int i = tid; i < CCH*IH*IW; i += NTHR) {
            int sx = i % IW;
            int t  = i / IW;
            int sy = t % IH;
            int c  = t / IH;
            int gx = gx0 + sx - 1, gy = gy0 + sy - 1;
            float v = 0.0f;
            if ((unsigned)gx < (unsigned)Ww && (unsigned)gy < (unsigned)Hh) {
                int hw = gy*Ww + gx;
                if (arow[hw])
                    v = src[(size_t)(n*CCH + c)*(Hh*Ww) + hw];
            }
            scf[(c*IH + sy)*IW + sx] = v;
        }
        __syncthreads();

        // ---- perception: sobel -> spf rows (cell stays in scf); 4 thr/pair ----
        {
            const int pair = tid & 127;          // 128 pixel-pairs
            const int q    = tid >> 7;           // 0..3 -> 4 channels each
            const int py = pair >> 3, px2 = pair & 7;
            const int sy = py + 1;
            #pragma unroll
            for (int cc = 0; cc < 4; cc++) {
                int c = 4*q + cc;
                const float2* r0 = (const float2*)(scf + (c*IH + sy - 1)*IW + 2*px2);
                const float2* r1 = (const float2*)((const float*)r0 + IW);
                const float2* r2 = (const float2*)((const float*)r1 + IW);
                float2 v00 = r0[0], v01 = r0[1];
                float2 v10 = r1[0], v11 = r1[1];
                float2 v20 = r2[0], v21 = r2[1];
                float a0=v00.x,a1=v00.y,a2=v01.x,a3=v01.y;
                float m0=v10.x,m1=v10.y,m2=v11.x,m3=v11.y;
                float q0=v20.x,q1=v20.y,q2=v21.x,q3=v21.y;
                float gxl = ((a2 - a0) + 2.f*(m2 - m0) + (q2 - q0)) * 0.125f;
                float gxh = ((a3 - a1) + 2.f*(m3 - m1) + (q3 - q1)) * 0.125f;
                float gyl = ((q0 - a0) + 2.f*(q1 - a1) + (q2 - a2)) * 0.125f;
                float gyh = ((q1 - a1) + 2.f*(q2 - a2) + (q3 - a3)) * 0.125f;
                *(float2*)(spf + c*NPX + 2*pair)        = make_float2(gxl, gxh);
                *(float2*)(spf + (16 + c)*NPX + 2*pair) = make_float2(gyl, gyh);
                if (c == 0) {
                    float t0 = fmaxf(fmaxf(a0,a1),a2);
                    float t1 = fmaxf(fmaxf(m0,m1),m2);
                    float t2 = fmaxf(fmaxf(q0,q1),q2);
                    float pl = fmaxf(fmaxf(t0,t1),t2);
                    float u0 = fmaxf(fmaxf(a1,a2),a3);
                    float u1 = fmaxf(fmaxf(m1,m2),m3);
                    float u2 = fmaxf(fmaxf(q1,q2),q3);
                    float ph = fmaxf(fmaxf(u0,u1),u2);
                    uchar2 pm;
                    pm.x = (pl > 0.1f) ? 1 : 0;
                    pm.y = (ph > 0.1f) ? 1 : 0;
                    *reinterpret_cast<uchar2*>(g_pre + (n*Hh + gy0 + py)*Ww + gx0 + 2*px2) = pm;
                }
            }
        }
        __syncthreads();

        // ---- GEMM1: H = relu(W1*perc); thread = (g in 128 px-lanes, ob of 12 o) ----
        {
            const int g  = tid & 127;    // px = g, g+128
            const int ob = tid >> 7;     // o = 12*ob .. 12*ob+11
            ULL acc[2][6];
            #pragma unroll
            for (int m = 0; m < 2; m++)
                #pragma unroll
                for (int j = 0; j < 6; j++) acc[m][j] = 0ull;

            const int off0 = (((g       ) >> 4) + 1)*IW + ((g       ) & 15) + 1;
            const int off1 = (((g + 128 ) >> 4) + 1)*IW + ((g + 128 ) & 15) + 1;

            // part A: k = 0..15, cell from scf
            #pragma unroll 4
            for (int k = 0; k < 16; k++) {
                float p0 = scf[k*(IH*IW) + off0];
                float p1 = scf[k*(IH*IW) + off1];
                ULL s0 = pk2(p0,p0), s1 = pk2(p1,p1);
                const ulonglong2* wv = (const ulonglong2*)(sw1f + k*48 + 12*ob);
                ulonglong2 w0 = wv[0], w1v = wv[1], w2v = wv[2];
                fma2(acc[0][0], s0, w0.x);  fma2(acc[1][0], s1, w0.x);
                fma2(acc[0][1], s0, w0.y);  fma2(acc[1][1], s1, w0.y);
                fma2(acc[0][2], s0, w1v.x); fma2(acc[1][2], s1, w1v.x);
                fma2(acc[0][3], s0, w1v.y); fma2(acc[1][3], s1, w1v.y);
                fma2(acc[0][4], s0, w2v.x); fma2(acc[1][4], s1, w2v.x);
                fma2(acc[0][5], s0, w2v.y); fma2(acc[1][5], s1, w2v.y);
            }
            // part B: k = 16..47, sobel from spf rows 0..31
            #pragma unroll 4
            for (int k2 = 0; k2 < 32; k2++) {
                const float* pr = spf + k2*NPX + g;
                float p0 = pr[0], p1 = pr[128];
                ULL s0 = pk2(p0,p0), s1 = pk2(p1,p1);
                const ulonglong2* wv = (const ulonglong2*)(sw1f + (16 + k2)*48 + 12*ob);
                ulonglong2 w0 = wv[0], w1v = wv[1], w2v = wv[2];
                fma2(acc[0][0], s0, w0.x);  fma2(acc[1][0], s1, w0.x);
                fma2(acc[0][1], s0, w0.y);  fma2(acc[1][1], s1, w0.y);
                fma2(acc[0][2], s0, w1v.x); fma2(acc[1][2], s1, w1v.x);
                fma2(acc[0][3], s0, w1v.y); fma2(acc[1][3], s1, w1v.y);
                fma2(acc[0][4], s0, w2v.x); fma2(acc[1][4], s1, w2v.x);
                fma2(acc[0][5], s0, w2v.y); fma2(acc[1][5], s1, w2v.y);
            }
            __syncthreads();   // spf reads done before H overwrites rows 0..31
            // store H: rows 0..31 -> spf, rows 32..47 -> shf (scf preserved!)
            #pragma unroll
            for (int op = 0; op < 6; op++) {
                int o = 12*ob + 2*op;          // even; pair (o,o+1) never straddles 32
                float* r0 = (o < 32) ? (spf + o*NPX) : (shf + (o - 32)*NPX);
                float* r1 = r0 + NPX;
                r0[g]       = fmaxf(lo2(acc[0][op]), 0.f);
                r0[g + 128] = fmaxf(lo2(acc[1][op]), 0.f);
                r1[g]       = fmaxf(hi2(acc[0][op]), 0.f);
                r1[g + 128] = fmaxf(hi2(acc[1][op]), 0.f);
            }
        }
        __syncthreads();

        // ---- GEMM2: cur = W2*H + residual(from scf); thread = (g2 in 128, jg of 4 j) ----
        {
            const int g2 = tid & 127;    // px = g2, g2+128
            const int jg = tid >> 7;     // j = 4*jg .. 4*jg+3
            const int pxA = g2, pxB = g2 + 128;
            const int pyA = pxA >> 4, sxA = pxA & 15;
            const int pyB = pxB >> 4, sxB = pxB & 15;
            const int hwA = (gy0 + pyA)*Ww + gx0 + sxA;
            const int hwB = (gy0 + pyB)*Ww + gx0 + sxB;
            const int soA = (pyA + 1)*IW + sxA + 1;
            const int soB = (pyB + 1)*IW + sxB + 1;

            // residual: masked cell straight from smem (scf already masked)
            float rA[4], rB[4];
            #pragma unroll
            for (int jj = 0; jj < 4; jj++) {
                int j = 4*jg + jj;
                rA[jj] = scf[j*(IH*IW) + soA];
                rB[jj] = scf[j*(IH*IW) + soB];
            }

            ULL cA[2], cB[2];
            cA[0] = cA[1] = cB[0] = cB[1] = 0ull;

            #pragma unroll 8
            for (int o = 0; o < 32; o++) {
                const float* hs = spf + o*NPX;
                float ha = hs[g2], hb = hs[g2 + 128];
                ULL sa = pk2(ha,ha), sb = pk2(hb,hb);
                const ulonglong2* wv = (const ulonglong2*)(sw2f + o*16 + 4*jg);
                ulonglong2 w0 = wv[0];
                fma2(cA[0], sa, w0.x); fma2(cA[1], sa, w0.y);
                fma2(cB[0], sb, w0.x); fma2(cB[1], sb, w0.y);
            }
            #pragma unroll 8
            for (int o = 32; o < 48; o++) {
                const float* hs = shf + (o - 32)*NPX;
                float ha = hs[g2], hb = hs[g2 + 128];
                ULL sa = pk2(ha,ha), sb = pk2(hb,hb);
                const ulonglong2* wv = (const ulonglong2*)(sw2f + o*16 + 4*jg);
                ulonglong2 w0 = wv[0];
                fma2(cA[0], sa, w0.x); fma2(cA[1], sa, w0.y);
                fma2(cB[0], sb, w0.x); fma2(cB[1], sb, w0.y);
            }

            // store with residual
            #pragma unroll
            for (int q = 0; q < 2; q++) {
                int j = 4*jg + 2*q;
                float* d0 = dst + (size_t)(n*CCH + j)*(Hh*Ww);
                float* d1 = d0 + Hh*Ww;
                d0[hwA] = lo2(cA[q]) + rA[2*q];
                d1[hwA] = hi2(cA[q]) + rA[2*q + 1];
                d0[hwB] = lo2(cB[q]) + rB[2*q];
                d1[hwB] = hi2(cB[q]) + rB[2*q + 1];
            }
        }
        __syncthreads();   // H/scf reads done before next tile's staging
    }
}

// Vectorized alive: 1 thread = 4 x-adjacent pixels. 9 loads vs 36.
__global__ void alive_kernel(float* __restrict__ outfinal, int parity, int writeOut)
{
    const float* __restrict__ cur = parity ? g_bufA : g_bufB;
    int t = blockIdx.x*blockDim.x + threadIdx.x;    // over NB*Hh*Ww/4
    if (t >= NB*Hh*Ww/4) return;
    const int x0 = (t % (Ww/4)) * 4;
    const int y  = (t / (Ww/4)) % Hh;
    const int n  = t / (Hh*Ww/4);
    const float* c0 = cur + (size_t)n*CCH*Hh*Ww;

    float m0 = -1e30f, m1 = -1e30f, m2 = -1e30f, m3 = -1e30f;
    const int yA = (y > 0) ? y - 1 : y;
    const int yB = (y < Hh-1) ? y + 1 : y;
    #pragma unroll
    for (int yy = yA; yy <= yB; yy++) {
        const float* row = c0 + yy*Ww;
        float4 v = *reinterpret_cast<const float4*>(row + x0);
        float l = (x0 > 0)      ? row[x0 - 1] : -1e30f;
        float r = (x0 + 4 < Ww) ? row[x0 + 4] : -1e30f;
        m0 = fmaxf(m0, fmaxf(l,   fmaxf(v.x, v.y)));
        m1 = fmaxf(m1, fmaxf(v.x, fmaxf(v.y, v.z)));
        m2 = fmaxf(m2, fmaxf(v.y, fmaxf(v.z, v.w)));
        m3 = fmaxf(m3, fmaxf(v.z, fmaxf(v.w, r)));
    }
    const int p = (n*Hh + y)*Ww + x0;
    uchar4 pre = *reinterpret_cast<const uchar4*>(g_pre + p);
    uchar4 al;
    al.x = (m0 > 0.1f && pre.x) ? 1 : 0;
    al.y = (m1 > 0.1f && pre.y) ? 1 : 0;
    al.z = (m2 > 0.1f && pre.z) ? 1 : 0;
    al.w = (m3 > 0.1f && pre.w) ? 1 : 0;
    *reinterpret_cast<uchar4*>(g_alive + p) = al;

    if (writeOut) {
        size_t base = ((size_t)n*CCH)*Hh*Ww + (size_t)y*Ww + x0;
        #pragma unroll
        for (int c = 1; c <= 10; c++) {
            float4 v = *reinterpret_cast<const float4*>(cur + base + (size_t)c*Hh*Ww);
            float4 o;
            o.x = al.x ? v.x : 0.0f;
            o.y = al.y ? v.y : 0.0f;
            o.z = al.z ? v.z : 0.0f;
            o.w = al.w ? v.w : 0.0f;
            *reinterpret_cast<float4*>(outfinal + (((size_t)n*10 + (c-1))*Hh + y)*Ww + x0) = o;
        }
    }
}

extern "C" void kernel_launch(void* const* d_in, const int* in_sizes, int n_in,
                              void* d_out, int out_size)
{
    const float *inp = nullptr, *w1 = nullptr, *w2 = nullptr;
    for (int i = 0; i < n_in; i++) {
        if (in_sizes[i] == 48*48)      w1 = (const float*)d_in[i];
        else if (in_sizes[i] == 16*48) w2 = (const float*)d_in[i];
        else                           inp = (const float*)d_in[i];
    }
    float* out = (float*)d_out;

    const int smemBytes = 20544*4;   // 82176 B
    cudaFuncSetAttribute(step_kernel, cudaFuncAttributeMaxDynamicSharedMemorySize, smemBytes);

    init_kernel<<<(NB*CCH*Hh*Ww + 255)/256, 256>>>(inp);

    const int g2 = (NB*Hh*Ww/4 + 255)/256;
    for (int it = 0; it < NITER; it++) {
        int parity = it & 1;
        step_kernel<<<NCTA, NTHR, smemBytes>>>(w1, w2, parity);
        alive_kernel<<<g2, 256>>>(out, parity, (it == NITER-1) ? 1 : 0);
    }
}